// round 3
// baseline (speedup 1.0000x reference)
#include <cuda_runtime.h>
#include <math.h>

#define BB 4096
#define TT 200
#define DD 64
#define H1 80
#define H2 40
#define NEG_BIG_F (-4294967295.0f)

typedef unsigned long long u64;

__device__ __forceinline__ u64 pack2(float lo, float hi) {
    u64 r; asm("mov.b64 %0, {%1, %2};" : "=l"(r) : "f"(lo), "f"(hi)); return r;
}
__device__ __forceinline__ void unpack2(u64 v, float& lo, float& hi) {
    asm("mov.b64 {%0, %1}, %2;" : "=f"(lo), "=f"(hi) : "l"(v));
}
__device__ __forceinline__ void fma2(u64& d, u64 a, u64 b) {
    asm("fma.rn.f32x2 %0, %1, %2, %0;" : "+l"(d) : "l"(a), "l"(b));
}

// One block per batch element b. 256 threads, 2 CTAs/SM.
// Phase 2 inner loops use packed fp32x2 FMA (FFMA2) to halve fma-pipe issue count.
__global__ __launch_bounds__(256, 2)
void din_attn_kernel(const float* __restrict__ q, const float* __restrict__ k,
                     const float* __restrict__ v, const int* __restrict__ mask,
                     const float* __restrict__ W1, const float* __restrict__ b1,
                     const float* __restrict__ W2, const float* __restrict__ b2,
                     const float* __restrict__ Wf, const float* __restrict__ bf,
                     float* __restrict__ out)
{
    __shared__ __align__(16) float q_sh[DD];
    __shared__ __align__(16) float Wk_sh[H1 * DD];    // [j][i]
    __shared__ __align__(16) float W2_sh[H1 * H2];    // [j][g]
    __shared__ __align__(16) float c_sh[H1];
    __shared__ __align__(16) float b2_sh[H2];
    __shared__ __align__(16) float Wf_sh[H2];
    __shared__ float sc_sh[TT];
    __shared__ float red_sh[8];
    __shared__ float part_sh[256];
    __shared__ float mx_sh, inv_sh;

    const int tid = threadIdx.x;
    const int b   = blockIdx.x;

    if (tid < DD) q_sh[tid] = q[b * DD + tid];
    __syncthreads();

    // ---- Phase 1: fold weights ----
    for (int idx = tid; idx < DD * H1; idx += 256) {
        int i = idx / H1;
        int j = idx % H1;
        float w = W1[(64 + i) * H1 + j]
                - W1[(128 + i) * H1 + j]
                + q_sh[i] * W1[(192 + i) * H1 + j];
        Wk_sh[j * DD + i] = w;
    }
    for (int idx = tid; idx < H1 * H2; idx += 256) W2_sh[idx] = W2[idx];
    if (tid < H2) { b2_sh[tid] = b2[tid]; Wf_sh[tid] = Wf[tid]; }
    if (tid < H1) {
        float acc = b1[tid];
        #pragma unroll 8
        for (int i = 0; i < DD; i++)
            acc += q_sh[i] * (W1[i * H1 + tid] + W1[(128 + i) * H1 + tid]);
        c_sh[tid] = acc;
    }
    __syncthreads();

    // ---- Phase 2: per-token MLP score (packed f32x2) ----
    if (tid < TT) {
        const ulonglong2* kp = (const ulonglong2*)(k + ((size_t)b * TT + tid) * DD);
        u64 kk2[32];
        #pragma unroll
        for (int ii = 0; ii < 16; ii++) {
            ulonglong2 t = kp[ii];
            kk2[2 * ii]     = t.x;
            kk2[2 * ii + 1] = t.y;
        }

        const int m0 = mask[(size_t)b * TT + tid];

        u64 h2a2[20];      // 40 packed H2 accumulators
        #pragma unroll
        for (int g = 0; g < 20; g++) {
            const float2 bb = ((const float2*)b2_sh)[g];
            h2a2[g] = pack2(bb.x, bb.y);
        }

        #pragma unroll 1
        for (int j = 0; j < H1; j += 2) {
            const ulonglong2* wrA = (const ulonglong2*)(Wk_sh + j * DD);
            const ulonglong2* wrB = (const ulonglong2*)(Wk_sh + (j + 1) * DD);
            u64 aA0 = 0ull, aA1 = 0ull, aA2 = 0ull, aA3 = 0ull;
            u64 aB0 = 0ull, aB1 = 0ull, aB2 = 0ull, aB3 = 0ull;
            #pragma unroll
            for (int ii = 0; ii < 16; ii += 2) {
                ulonglong2 wA0 = wrA[ii];
                ulonglong2 wA1 = wrA[ii + 1];
                ulonglong2 wB0 = wrB[ii];
                ulonglong2 wB1 = wrB[ii + 1];
                fma2(aA0, kk2[2 * ii],     wA0.x);
                fma2(aA1, kk2[2 * ii + 1], wA0.y);
                fma2(aA2, kk2[2 * ii + 2], wA1.x);
                fma2(aA3, kk2[2 * ii + 3], wA1.y);
                fma2(aB0, kk2[2 * ii],     wB0.x);
                fma2(aB1, kk2[2 * ii + 1], wB0.y);
                fma2(aB2, kk2[2 * ii + 2], wB1.x);
                fma2(aB3, kk2[2 * ii + 3], wB1.y);
            }
            float xa, ya, xb, yb, xc, yc, xd, yd;
            unpack2(aA0, xa, ya); unpack2(aA1, xb, yb);
            unpack2(aA2, xc, yc); unpack2(aA3, xd, yd);
            float hA = fmaxf(c_sh[j] + (((xa + ya) + (xb + yb)) + ((xc + yc) + (xd + yd))), 0.0f);
            unpack2(aB0, xa, ya); unpack2(aB1, xb, yb);
            unpack2(aB2, xc, yc); unpack2(aB3, xd, yd);
            float hB = fmaxf(c_sh[j + 1] + (((xa + ya) + (xb + yb)) + ((xc + yc) + (xd + yd))), 0.0f);

            const u64 hA2 = pack2(hA, hA);
            const u64 hB2 = pack2(hB, hB);
            const ulonglong2* w2A = (const ulonglong2*)(W2_sh + j * H2);
            const ulonglong2* w2B = (const ulonglong2*)(W2_sh + (j + 1) * H2);
            #pragma unroll
            for (int g = 0; g < 10; g++) {
                ulonglong2 wA = w2A[g];
                ulonglong2 wB = w2B[g];
                fma2(h2a2[2 * g],     hA2, wA.x);
                fma2(h2a2[2 * g + 1], hA2, wA.y);
                fma2(h2a2[2 * g],     hB2, wB.x);
                fma2(h2a2[2 * g + 1], hB2, wB.y);
            }
        }

        float s = bf[0];
        #pragma unroll
        for (int g = 0; g < 20; g++) {
            float lo, hi;
            unpack2(h2a2[g], lo, hi);
            s = fmaf(fmaxf(lo, 0.0f), Wf_sh[2 * g],     s);
            s = fmaf(fmaxf(hi, 0.0f), Wf_sh[2 * g + 1], s);
        }
        if (m0 == 0) s = NEG_BIG_F;
        sc_sh[tid] = s;
    }
    __syncthreads();

    // ---- Phase 3: softmax over T ----
    float mval = (tid < TT) ? sc_sh[tid] : -3.0e38f;
    #pragma unroll
    for (int o = 16; o; o >>= 1)
        mval = fmaxf(mval, __shfl_xor_sync(0xffffffffu, mval, o));
    if ((tid & 31) == 0) red_sh[tid >> 5] = mval;
    __syncthreads();
    if (tid == 0) {
        float m = red_sh[0];
        #pragma unroll
        for (int w = 1; w < 8; w++) m = fmaxf(m, red_sh[w]);
        mx_sh = m;
    }
    __syncthreads();
    const float mx = mx_sh;
    float e = (tid < TT) ? __expf(sc_sh[tid] - mx) : 0.0f;
    if (tid < TT) sc_sh[tid] = e;
    float sval = e;
    #pragma unroll
    for (int o = 16; o; o >>= 1)
        sval += __shfl_xor_sync(0xffffffffu, sval, o);
    if ((tid & 31) == 0) red_sh[tid >> 5] = sval;
    __syncthreads();
    if (tid == 0) {
        float sm = 0.0f;
        #pragma unroll
        for (int w = 0; w < 8; w++) sm += red_sh[w];
        inv_sh = 1.0f / sm;
    }
    __syncthreads();

    // ---- Phase 4: out = attn @ V ----
    const float inv = inv_sh;
    const int dd = tid & 63;
    const int p  = tid >> 6;
    const float* vb = v + (size_t)b * TT * DD;
    float a0 = 0.f, a1 = 0.f;
    const int t0 = p * 50;
    #pragma unroll 5
    for (int t = t0; t < t0 + 50; t += 2) {
        a0 = fmaf(sc_sh[t],     vb[(size_t)t * DD + dd],       a0);
        a1 = fmaf(sc_sh[t + 1], vb[(size_t)(t + 1) * DD + dd], a1);
    }
    part_sh[tid] = a0 + a1;
    __syncthreads();
    if (tid < DD) {
        float r = part_sh[tid] + part_sh[tid + 64] + part_sh[tid + 128] + part_sh[tid + 192];
        out[(size_t)b * DD + tid] = r * inv;
    }
}

extern "C" void kernel_launch(void* const* d_in, const int* in_sizes, int n_in,
                              void* d_out, int out_size)
{
    const float* q    = (const float*)d_in[0];
    const float* k    = (const float*)d_in[1];
    const float* v    = (const float*)d_in[2];
    const int*   mask = (const int*)  d_in[3];
    const float* W1   = (const float*)d_in[4];
    const float* b1   = (const float*)d_in[5];
    const float* W2   = (const float*)d_in[6];
    const float* b2   = (const float*)d_in[7];
    const float* Wf   = (const float*)d_in[8];
    const float* bf   = (const float*)d_in[9];
    float* out = (float*)d_out;

    din_attn_kernel<<<BB, 256>>>(q, k, v, mask, W1, b1, W2, b2, Wf, bf, out);
}

// round 4
// speedup vs baseline: 1.0002x; 1.0002x over previous
#include <cuda_runtime.h>
#include <math.h>

#define BB 4096
#define TT 200
#define DD 64
#define H1 80
#define H2 40
#define NEG_BIG_F (-4294967295.0f)

typedef unsigned long long u64;

__device__ __forceinline__ u64 pack2(float lo, float hi) {
    u64 r; asm("mov.b64 %0, {%1, %2};" : "=l"(r) : "f"(lo), "f"(hi)); return r;
}
__device__ __forceinline__ void unpack2(u64 v, float& lo, float& hi) {
    asm("mov.b64 {%0, %1}, %2;" : "=f"(lo), "=f"(hi) : "l"(v));
}
__device__ __forceinline__ void fma2(u64& d, u64 a, u64 b) {
    asm("fma.rn.f32x2 %0, %1, %2, %0;" : "+l"(d) : "l"(a), "l"(b));
}

// One block per batch element b. 256 threads, 2 CTAs/SM.
// Phase 2 inner loops use packed fp32x2 FMA (FFMA2) to halve fma-pipe issue count.
__global__ __launch_bounds__(256, 2)
void din_attn_kernel(const float* __restrict__ q, const float* __restrict__ k,
                     const float* __restrict__ v, const int* __restrict__ mask,
                     const float* __restrict__ W1, const float* __restrict__ b1,
                     const float* __restrict__ W2, const float* __restrict__ b2,
                     const float* __restrict__ Wf, const float* __restrict__ bf,
                     float* __restrict__ out)
{
    __shared__ __align__(16) float q_sh[DD];
    __shared__ __align__(16) float Wk_sh[H1 * DD];    // [j][i]
    __shared__ __align__(16) float W2_sh[H1 * H2];    // [j][g]
    __shared__ __align__(16) float c_sh[H1];
    __shared__ __align__(16) float b2_sh[H2];
    __shared__ __align__(16) float Wf_sh[H2];
    __shared__ float sc_sh[TT];
    __shared__ float red_sh[8];
    __shared__ float part_sh[256];
    __shared__ float mx_sh, inv_sh;

    const int tid = threadIdx.x;
    const int b   = blockIdx.x;

    if (tid < DD) q_sh[tid] = q[b * DD + tid];
    __syncthreads();

    // ---- Phase 1: fold weights ----
    for (int idx = tid; idx < DD * H1; idx += 256) {
        int i = idx / H1;
        int j = idx % H1;
        float w = W1[(64 + i) * H1 + j]
                - W1[(128 + i) * H1 + j]
                + q_sh[i] * W1[(192 + i) * H1 + j];
        Wk_sh[j * DD + i] = w;
    }
    for (int idx = tid; idx < H1 * H2; idx += 256) W2_sh[idx] = W2[idx];
    if (tid < H2) { b2_sh[tid] = b2[tid]; Wf_sh[tid] = Wf[tid]; }
    if (tid < H1) {
        float acc = b1[tid];
        #pragma unroll 8
        for (int i = 0; i < DD; i++)
            acc += q_sh[i] * (W1[i * H1 + tid] + W1[(128 + i) * H1 + tid]);
        c_sh[tid] = acc;
    }
    __syncthreads();

    // ---- Phase 2: per-token MLP score (packed f32x2) ----
    if (tid < TT) {
        const ulonglong2* kp = (const ulonglong2*)(k + ((size_t)b * TT + tid) * DD);
        u64 kk2[32];
        #pragma unroll
        for (int ii = 0; ii < 16; ii++) {
            ulonglong2 t = kp[ii];
            kk2[2 * ii]     = t.x;
            kk2[2 * ii + 1] = t.y;
        }

        const int m0 = mask[(size_t)b * TT + tid];

        u64 h2a2[20];      // 40 packed H2 accumulators
        #pragma unroll
        for (int g = 0; g < 20; g++) {
            const float2 bb = ((const float2*)b2_sh)[g];
            h2a2[g] = pack2(bb.x, bb.y);
        }

        #pragma unroll 1
        for (int j = 0; j < H1; j += 2) {
            const ulonglong2* wrA = (const ulonglong2*)(Wk_sh + j * DD);
            const ulonglong2* wrB = (const ulonglong2*)(Wk_sh + (j + 1) * DD);
            u64 aA0 = 0ull, aA1 = 0ull, aA2 = 0ull, aA3 = 0ull;
            u64 aB0 = 0ull, aB1 = 0ull, aB2 = 0ull, aB3 = 0ull;
            #pragma unroll
            for (int ii = 0; ii < 16; ii += 2) {
                ulonglong2 wA0 = wrA[ii];
                ulonglong2 wA1 = wrA[ii + 1];
                ulonglong2 wB0 = wrB[ii];
                ulonglong2 wB1 = wrB[ii + 1];
                fma2(aA0, kk2[2 * ii],     wA0.x);
                fma2(aA1, kk2[2 * ii + 1], wA0.y);
                fma2(aA2, kk2[2 * ii + 2], wA1.x);
                fma2(aA3, kk2[2 * ii + 3], wA1.y);
                fma2(aB0, kk2[2 * ii],     wB0.x);
                fma2(aB1, kk2[2 * ii + 1], wB0.y);
                fma2(aB2, kk2[2 * ii + 2], wB1.x);
                fma2(aB3, kk2[2 * ii + 3], wB1.y);
            }
            float xa, ya, xb, yb, xc, yc, xd, yd;
            unpack2(aA0, xa, ya); unpack2(aA1, xb, yb);
            unpack2(aA2, xc, yc); unpack2(aA3, xd, yd);
            float hA = fmaxf(c_sh[j] + (((xa + ya) + (xb + yb)) + ((xc + yc) + (xd + yd))), 0.0f);
            unpack2(aB0, xa, ya); unpack2(aB1, xb, yb);
            unpack2(aB2, xc, yc); unpack2(aB3, xd, yd);
            float hB = fmaxf(c_sh[j + 1] + (((xa + ya) + (xb + yb)) + ((xc + yc) + (xd + yd))), 0.0f);

            const u64 hA2 = pack2(hA, hA);
            const u64 hB2 = pack2(hB, hB);
            const ulonglong2* w2A = (const ulonglong2*)(W2_sh + j * H2);
            const ulonglong2* w2B = (const ulonglong2*)(W2_sh + (j + 1) * H2);
            #pragma unroll
            for (int g = 0; g < 10; g++) {
                ulonglong2 wA = w2A[g];
                ulonglong2 wB = w2B[g];
                fma2(h2a2[2 * g],     hA2, wA.x);
                fma2(h2a2[2 * g + 1], hA2, wA.y);
                fma2(h2a2[2 * g],     hB2, wB.x);
                fma2(h2a2[2 * g + 1], hB2, wB.y);
            }
        }

        float s = bf[0];
        #pragma unroll
        for (int g = 0; g < 20; g++) {
            float lo, hi;
            unpack2(h2a2[g], lo, hi);
            s = fmaf(fmaxf(lo, 0.0f), Wf_sh[2 * g],     s);
            s = fmaf(fmaxf(hi, 0.0f), Wf_sh[2 * g + 1], s);
        }
        if (m0 == 0) s = NEG_BIG_F;
        sc_sh[tid] = s;
    }
    __syncthreads();

    // ---- Phase 3: softmax over T ----
    float mval = (tid < TT) ? sc_sh[tid] : -3.0e38f;
    #pragma unroll
    for (int o = 16; o; o >>= 1)
        mval = fmaxf(mval, __shfl_xor_sync(0xffffffffu, mval, o));
    if ((tid & 31) == 0) red_sh[tid >> 5] = mval;
    __syncthreads();
    if (tid == 0) {
        float m = red_sh[0];
        #pragma unroll
        for (int w = 1; w < 8; w++) m = fmaxf(m, red_sh[w]);
        mx_sh = m;
    }
    __syncthreads();
    const float mx = mx_sh;
    float e = (tid < TT) ? __expf(sc_sh[tid] - mx) : 0.0f;
    if (tid < TT) sc_sh[tid] = e;
    float sval = e;
    #pragma unroll
    for (int o = 16; o; o >>= 1)
        sval += __shfl_xor_sync(0xffffffffu, sval, o);
    if ((tid & 31) == 0) red_sh[tid >> 5] = sval;
    __syncthreads();
    if (tid == 0) {
        float sm = 0.0f;
        #pragma unroll
        for (int w = 0; w < 8; w++) sm += red_sh[w];
        inv_sh = 1.0f / sm;
    }
    __syncthreads();

    // ---- Phase 4: out = attn @ V ----
    const float inv = inv_sh;
    const int dd = tid & 63;
    const int p  = tid >> 6;
    const float* vb = v + (size_t)b * TT * DD;
    float a0 = 0.f, a1 = 0.f;
    const int t0 = p * 50;
    #pragma unroll 5
    for (int t = t0; t < t0 + 50; t += 2) {
        a0 = fmaf(sc_sh[t],     vb[(size_t)t * DD + dd],       a0);
        a1 = fmaf(sc_sh[t + 1], vb[(size_t)(t + 1) * DD + dd], a1);
    }
    part_sh[tid] = a0 + a1;
    __syncthreads();
    if (tid < DD) {
        float r = part_sh[tid] + part_sh[tid + 64] + part_sh[tid + 128] + part_sh[tid + 192];
        out[(size_t)b * DD + tid] = r * inv;
    }
}

extern "C" void kernel_launch(void* const* d_in, const int* in_sizes, int n_in,
                              void* d_out, int out_size)
{
    const float* q    = (const float*)d_in[0];
    const float* k    = (const float*)d_in[1];
    const float* v    = (const float*)d_in[2];
    const int*   mask = (const int*)  d_in[3];
    const float* W1   = (const float*)d_in[4];
    const float* b1   = (const float*)d_in[5];
    const float* W2   = (const float*)d_in[6];
    const float* b2   = (const float*)d_in[7];
    const float* Wf   = (const float*)d_in[8];
    const float* bf   = (const float*)d_in[9];
    float* out = (float*)d_out;

    din_attn_kernel<<<BB, 256>>>(q, k, v, mask, W1, b1, W2, b2, Wf, bf, out);
}

// round 5
// speedup vs baseline: 1.1780x; 1.1778x over previous
#include <cuda_runtime.h>
#include <math.h>

#define BB 4096
#define TT 200
#define DD 64
#define H1 80
#define H2 40
#define NEG_BIG_F (-4294967295.0f)
#define S1S 84   // S1 row stride in floats (16B-aligned rows)

typedef unsigned long long u64;

__device__ __forceinline__ u64 pack2(float lo, float hi) {
    u64 r; asm("mov.b64 %0, {%1, %2};" : "=l"(r) : "f"(lo), "f"(hi)); return r;
}
__device__ __forceinline__ void unpack2(u64 v, float& lo, float& hi) {
    asm("mov.b64 {%0, %1}, %2;" : "=f"(lo), "=f"(hi) : "l"(v));
}
__device__ __forceinline__ void fma2(u64& d, u64 a, u64 b) {
    asm("fma.rn.f32x2 %0, %1, %2, %0;" : "+l"(d) : "l"(a), "l"(b));
}

__device__ __forceinline__ void relu_store8(const u64* a, float* dst) {
    float x0,x1,x2,x3,x4,x5,x6,x7;
    unpack2(a[0],x0,x1); unpack2(a[1],x2,x3);
    unpack2(a[2],x4,x5); unpack2(a[3],x6,x7);
    ((float4*)dst)[0] = make_float4(fmaxf(x0,0.f),fmaxf(x1,0.f),fmaxf(x2,0.f),fmaxf(x3,0.f));
    ((float4*)dst)[1] = make_float4(fmaxf(x4,0.f),fmaxf(x5,0.f),fmaxf(x6,0.f),fmaxf(x7,0.f));
}

__device__ __forceinline__ float relu_dot8(const u64* a, const float* wf) {
    float x0,x1,x2,x3,x4,x5,x6,x7;
    unpack2(a[0],x0,x1); unpack2(a[1],x2,x3);
    unpack2(a[2],x4,x5); unpack2(a[3],x6,x7);
    float s = fmaxf(x0,0.f)*wf[0];
    s = fmaf(fmaxf(x1,0.f), wf[1], s);
    s = fmaf(fmaxf(x2,0.f), wf[2], s);
    s = fmaf(fmaxf(x3,0.f), wf[3], s);
    s = fmaf(fmaxf(x4,0.f), wf[4], s);
    s = fmaf(fmaxf(x5,0.f), wf[5], s);
    s = fmaf(fmaxf(x6,0.f), wf[6], s);
    s = fmaf(fmaxf(x7,0.f), wf[7], s);
    return s;
}

// smem float offsets
#define OFF_Q      0
#define OFF_WK     (OFF_Q + 64)           // Wk transposed [64][80]
#define OFF_C      (OFF_WK + 64*80)       // [80]
#define OFF_W2     (OFF_C + 80)           // [80][40]
#define OFF_B2     (OFF_W2 + 80*40)       // [40]
#define OFF_WF     (OFF_B2 + 40)          // [40]
#define OFF_S1     (OFF_WF + 40)          // [200][S1S]
#define OFF_P2     (OFF_S1 + 200*S1S)     // [200*5]
#define OFF_SC     (OFF_P2 + 1000)        // [200]
#define OFF_RED    (OFF_SC + 200)         // [8]
#define OFF_PART   (OFF_RED + 8)          // [256]
#define OFF_MXINV  (OFF_PART + 256)       // [2]
#define SMEM_FLOATS (OFF_MXINV + 2)

__global__ __launch_bounds__(256, 2)
void din_attn_kernel(const float* __restrict__ q, const float* __restrict__ kin,
                     const float* __restrict__ v, const int* __restrict__ mask,
                     const float* __restrict__ W1, const float* __restrict__ b1,
                     const float* __restrict__ W2, const float* __restrict__ b2,
                     const float* __restrict__ Wf, const float* __restrict__ bf,
                     float* __restrict__ out)
{
    extern __shared__ float sm[];
    float* q_sh = sm + OFF_Q;
    float* Wk   = sm + OFF_WK;
    float* c_sh = sm + OFF_C;
    float* W2s  = sm + OFF_W2;
    float* b2s  = sm + OFF_B2;
    float* Wfs  = sm + OFF_WF;
    float* S1   = sm + OFF_S1;
    float* p2   = sm + OFF_P2;
    float* sc   = sm + OFF_SC;
    float* red  = sm + OFF_RED;
    float* part = sm + OFF_PART;
    float* mxin = sm + OFF_MXINV;

    const int tid = threadIdx.x;
    const int b   = blockIdx.x;

    if (tid < DD) q_sh[tid] = q[b * DD + tid];
    __syncthreads();

    // ---- fold W1 into Wk^T [i][j] + bias c ----
    for (int idx = tid; idx < DD * H1; idx += 256) {
        int i = idx / H1;
        int j = idx - i * H1;
        Wk[i * H1 + j] = W1[(64 + i) * H1 + j]
                       - W1[(128 + i) * H1 + j]
                       + q_sh[i] * W1[(192 + i) * H1 + j];
    }
    for (int idx = tid; idx < H1 * H2; idx += 256) W2s[idx] = W2[idx];
    if (tid < H2) { b2s[tid] = b2[tid]; Wfs[tid] = Wf[tid]; }
    if (tid < H1) {
        float acc = b1[tid];
        #pragma unroll 8
        for (int i = 0; i < DD; i++)
            acc += q_sh[i] * (W1[i * H1 + tid] + W1[(128 + i) * H1 + tid]);
        c_sh[tid] = acc;
    }
    __syncthreads();

    // ---- GEMM1: S1[200][80] = relu(c + K @ Wk^T), 4tok x 8j tiles ----
    if (tid < 250) {
        #pragma unroll 1
        for (int pass = 0; pass < 2; pass++) {
            const int tile = tid + pass * 250;
            const int tg = tile / 10;
            const int jg = tile - tg * 10;
            const int jc = jg * 8;
            const float* kb = kin + ((size_t)b * TT + tg * 4) * DD;

            u64 acc[4][4];
            {
                u64 c0 = pack2(c_sh[jc],     c_sh[jc + 1]);
                u64 c1 = pack2(c_sh[jc + 2], c_sh[jc + 3]);
                u64 c2 = pack2(c_sh[jc + 4], c_sh[jc + 5]);
                u64 c3 = pack2(c_sh[jc + 6], c_sh[jc + 7]);
                #pragma unroll
                for (int tt = 0; tt < 4; tt++) {
                    acc[tt][0] = c0; acc[tt][1] = c1; acc[tt][2] = c2; acc[tt][3] = c3;
                }
            }

            #pragma unroll 2
            for (int i = 0; i < DD; i += 4) {
                float kr[4][4];
                *(float4*)kr[0] = *(const float4*)(kb + 0 * DD + i);
                *(float4*)kr[1] = *(const float4*)(kb + 1 * DD + i);
                *(float4*)kr[2] = *(const float4*)(kb + 2 * DD + i);
                *(float4*)kr[3] = *(const float4*)(kb + 3 * DD + i);
                #pragma unroll
                for (int ii = 0; ii < 4; ii++) {
                    const ulonglong2* wr = (const ulonglong2*)(Wk + (i + ii) * H1 + jc);
                    ulonglong2 wA = wr[0];
                    ulonglong2 wB = wr[1];
                    #pragma unroll
                    for (int tt = 0; tt < 4; tt++) {
                        u64 s = pack2(kr[tt][ii], kr[tt][ii]);
                        fma2(acc[tt][0], s, wA.x);
                        fma2(acc[tt][1], s, wA.y);
                        fma2(acc[tt][2], s, wB.x);
                        fma2(acc[tt][3], s, wB.y);
                    }
                }
            }
            #pragma unroll
            for (int tt = 0; tt < 4; tt++)
                relu_store8(acc[tt], S1 + (tg * 4 + tt) * S1S + jc);
        }
    }
    __syncthreads();

    // ---- GEMM2: S2[200][40] = relu(b2 + S1 @ W2), 4tok x 8g tiles; fold Wf ----
    if (tid < 250) {
        const int tg = tid / 5;
        const int gg = tid - tg * 5;
        const int gc = gg * 8;
        const float* s1b = S1 + (size_t)(tg * 4) * S1S;

        u64 acc[4][4];
        {
            u64 c0 = pack2(b2s[gc],     b2s[gc + 1]);
            u64 c1 = pack2(b2s[gc + 2], b2s[gc + 3]);
            u64 c2 = pack2(b2s[gc + 4], b2s[gc + 5]);
            u64 c3 = pack2(b2s[gc + 6], b2s[gc + 7]);
            #pragma unroll
            for (int tt = 0; tt < 4; tt++) {
                acc[tt][0] = c0; acc[tt][1] = c1; acc[tt][2] = c2; acc[tt][3] = c3;
            }
        }

        #pragma unroll 2
        for (int j = 0; j < H1; j += 4) {
            float sr[4][4];
            *(float4*)sr[0] = *(const float4*)(s1b + 0 * S1S + j);
            *(float4*)sr[1] = *(const float4*)(s1b + 1 * S1S + j);
            *(float4*)sr[2] = *(const float4*)(s1b + 2 * S1S + j);
            *(float4*)sr[3] = *(const float4*)(s1b + 3 * S1S + j);
            #pragma unroll
            for (int ji = 0; ji < 4; ji++) {
                const ulonglong2* wr = (const ulonglong2*)(W2s + (j + ji) * H2 + gc);
                ulonglong2 wA = wr[0];
                ulonglong2 wB = wr[1];
                #pragma unroll
                for (int tt = 0; tt < 4; tt++) {
                    u64 s = pack2(sr[tt][ji], sr[tt][ji]);
                    fma2(acc[tt][0], s, wA.x);
                    fma2(acc[tt][1], s, wA.y);
                    fma2(acc[tt][2], s, wB.x);
                    fma2(acc[tt][3], s, wB.y);
                }
            }
        }
        float wf[8];
        *(float4*)wf       = *(const float4*)(Wfs + gc);
        *(float4*)(wf + 4) = *(const float4*)(Wfs + gc + 4);
        #pragma unroll
        for (int tt = 0; tt < 4; tt++)
            p2[(tg * 4 + tt) * 5 + gg] = relu_dot8(acc[tt], wf);
    }
    __syncthreads();

    // ---- score assembly + softmax ----
    if (tid < TT) {
        float s = bf[0] + ((p2[tid * 5] + p2[tid * 5 + 1]) +
                           (p2[tid * 5 + 2] + p2[tid * 5 + 3]) + p2[tid * 5 + 4]);
        if (mask[(size_t)b * TT + tid] == 0) s = NEG_BIG_F;
        sc[tid] = s;
    }
    __syncthreads();

    float mval = (tid < TT) ? sc[tid] : -3.0e38f;
    #pragma unroll
    for (int o = 16; o; o >>= 1)
        mval = fmaxf(mval, __shfl_xor_sync(0xffffffffu, mval, o));
    if ((tid & 31) == 0) red[tid >> 5] = mval;
    __syncthreads();
    if (tid == 0) {
        float m = red[0];
        #pragma unroll
        for (int w = 1; w < 8; w++) m = fmaxf(m, red[w]);
        mxin[0] = m;
    }
    __syncthreads();
    const float mx = mxin[0];
    float e = (tid < TT) ? __expf(sc[tid] - mx) : 0.0f;
    if (tid < TT) sc[tid] = e;
    float sval = e;
    #pragma unroll
    for (int o = 16; o; o >>= 1)
        sval += __shfl_xor_sync(0xffffffffu, sval, o);
    if ((tid & 31) == 0) red[tid >> 5] = sval;
    __syncthreads();
    if (tid == 0) {
        float smv = 0.0f;
        #pragma unroll
        for (int w = 0; w < 8; w++) smv += red[w];
        mxin[1] = 1.0f / smv;
    }
    __syncthreads();

    // ---- out = attn @ V ----
    const float inv = mxin[1];
    const int dd = tid & 63;
    const int p  = tid >> 6;
    const float* vb = v + (size_t)b * TT * DD;
    float a0 = 0.f, a1 = 0.f;
    const int t0 = p * 50;
    #pragma unroll 5
    for (int t = t0; t < t0 + 50; t += 2) {
        a0 = fmaf(sc[t],     vb[(size_t)t * DD + dd],       a0);
        a1 = fmaf(sc[t + 1], vb[(size_t)(t + 1) * DD + dd], a1);
    }
    part[tid] = a0 + a1;
    __syncthreads();
    if (tid < DD) {
        float r = part[tid] + part[tid + 64] + part[tid + 128] + part[tid + 192];
        out[(size_t)b * DD + tid] = r * inv;
    }
}

extern "C" void kernel_launch(void* const* d_in, const int* in_sizes, int n_in,
                              void* d_out, int out_size)
{
    const float* q    = (const float*)d_in[0];
    const float* k    = (const float*)d_in[1];
    const float* v    = (const float*)d_in[2];
    const int*   mask = (const int*)  d_in[3];
    const float* W1   = (const float*)d_in[4];
    const float* b1   = (const float*)d_in[5];
    const float* W2   = (const float*)d_in[6];
    const float* b2   = (const float*)d_in[7];
    const float* Wf   = (const float*)d_in[8];
    const float* bf   = (const float*)d_in[9];
    float* out = (float*)d_out;

    const int smem_bytes = SMEM_FLOATS * (int)sizeof(float);
    cudaFuncSetAttribute(din_attn_kernel,
                         cudaFuncAttributeMaxDynamicSharedMemorySize, smem_bytes);
    din_attn_kernel<<<BB, 256, smem_bytes>>>(q, k, v, mask, W1, b1, W2, b2, Wf, bf, out);
}

// round 6
// speedup vs baseline: 1.2589x; 1.0686x over previous
#include <cuda_runtime.h>
#include <math.h>

#define BB 4096
#define TT 200
#define DD 64
#define H1 80
#define H2 40
#define NEG_BIG_F (-4294967295.0f)
#define S1S 84   // S1 row stride in floats (16B-aligned rows)

typedef unsigned long long u64;

__device__ __forceinline__ u64 pack2(float lo, float hi) {
    u64 r; asm("mov.b64 %0, {%1, %2};" : "=l"(r) : "f"(lo), "f"(hi)); return r;
}
__device__ __forceinline__ void unpack2(u64 v, float& lo, float& hi) {
    asm("mov.b64 {%0, %1}, %2;" : "=f"(lo), "=f"(hi) : "l"(v));
}
__device__ __forceinline__ void fma2(u64& d, u64 a, u64 b) {
    asm("fma.rn.f32x2 %0, %1, %2, %0;" : "+l"(d) : "l"(a), "l"(b));
}

__device__ __forceinline__ void relu_store8(const u64* a, float* dst) {
    float x0,x1,x2,x3,x4,x5,x6,x7;
    unpack2(a[0],x0,x1); unpack2(a[1],x2,x3);
    unpack2(a[2],x4,x5); unpack2(a[3],x6,x7);
    ((float4*)dst)[0] = make_float4(fmaxf(x0,0.f),fmaxf(x1,0.f),fmaxf(x2,0.f),fmaxf(x3,0.f));
    ((float4*)dst)[1] = make_float4(fmaxf(x4,0.f),fmaxf(x5,0.f),fmaxf(x6,0.f),fmaxf(x7,0.f));
}

__device__ __forceinline__ float relu_dot8(const u64* a, const float* wf) {
    float x0,x1,x2,x3,x4,x5,x6,x7;
    unpack2(a[0],x0,x1); unpack2(a[1],x2,x3);
    unpack2(a[2],x4,x5); unpack2(a[3],x6,x7);
    float s = fmaxf(x0,0.f)*wf[0];
    s = fmaf(fmaxf(x1,0.f), wf[1], s);
    s = fmaf(fmaxf(x2,0.f), wf[2], s);
    s = fmaf(fmaxf(x3,0.f), wf[3], s);
    s = fmaf(fmaxf(x4,0.f), wf[4], s);
    s = fmaf(fmaxf(x5,0.f), wf[5], s);
    s = fmaf(fmaxf(x6,0.f), wf[6], s);
    s = fmaf(fmaxf(x7,0.f), wf[7], s);
    return s;
}

// smem float offsets
#define OFF_Q      0
#define OFF_WK     (OFF_Q + 64)           // Wk transposed [64][80]
#define OFF_C      (OFF_WK + 64*80)       // [80]
#define OFF_W2     (OFF_C + 80)           // [80][40]
#define OFF_B2     (OFF_W2 + 80*40)       // [40]
#define OFF_WF     (OFF_B2 + 40)          // [40]
#define OFF_S1     (OFF_WF + 40)          // [200][S1S]
#define OFF_P2     (OFF_S1 + 200*S1S)     // [200*5]
#define OFF_SC     (OFF_P2 + 1000)        // [200]
#define OFF_RED    (OFF_SC + 200)         // [8]
#define OFF_PART   (OFF_RED + 8)          // [256]
#define OFF_MXINV  (OFF_PART + 256)       // [2]
#define SMEM_FLOATS (OFF_MXINV + 2)

__global__ __launch_bounds__(256, 2)
void din_attn_kernel(const float* __restrict__ q, const float* __restrict__ kin,
                     const float* __restrict__ v, const int* __restrict__ mask,
                     const float* __restrict__ W1, const float* __restrict__ b1,
                     const float* __restrict__ W2, const float* __restrict__ b2,
                     const float* __restrict__ Wf, const float* __restrict__ bf,
                     float* __restrict__ out)
{
    extern __shared__ float sm[];
    float* q_sh = sm + OFF_Q;
    float* Wk   = sm + OFF_WK;
    float* c_sh = sm + OFF_C;
    float* W2s  = sm + OFF_W2;
    float* b2s  = sm + OFF_B2;
    float* Wfs  = sm + OFF_WF;
    float* S1   = sm + OFF_S1;
    float* p2   = sm + OFF_P2;
    float* sc   = sm + OFF_SC;
    float* red  = sm + OFF_RED;
    float* part = sm + OFF_PART;
    float* mxin = sm + OFF_MXINV;

    const int tid = threadIdx.x;
    const int b   = blockIdx.x;

    if (tid < DD) q_sh[tid] = q[b * DD + tid];
    __syncthreads();

    // ---- fold W1 into Wk^T [i][j] + bias c ----
    for (int idx = tid; idx < DD * H1; idx += 256) {
        int i = idx / H1;
        int j = idx - i * H1;
        Wk[i * H1 + j] = W1[(64 + i) * H1 + j]
                       - W1[(128 + i) * H1 + j]
                       + q_sh[i] * W1[(192 + i) * H1 + j];
    }
    for (int idx = tid; idx < H1 * H2; idx += 256) W2s[idx] = W2[idx];
    if (tid < H2) { b2s[tid] = b2[tid]; Wfs[tid] = Wf[tid]; }
    if (tid < H1) {
        float acc = b1[tid];
        #pragma unroll 8
        for (int i = 0; i < DD; i++)
            acc += q_sh[i] * (W1[i * H1 + tid] + W1[(128 + i) * H1 + tid]);
        c_sh[tid] = acc;
    }
    __syncthreads();

    // ---- GEMM1: S1[200][80] = relu(c + K @ Wk^T), 8tok x 8j tiles ----
    if (tid < 250) {
        const int tg = tid / 10;          // 0..24 -> tokens tg*8..tg*8+7
        const int jg = tid - tg * 10;     // 0..9  -> j cols jg*8..+7
        const int jc = jg * 8;
        const float* kb = kin + ((size_t)b * TT + tg * 8) * DD;

        u64 acc[8][4];
        {
            u64 c0 = pack2(c_sh[jc],     c_sh[jc + 1]);
            u64 c1 = pack2(c_sh[jc + 2], c_sh[jc + 3]);
            u64 c2 = pack2(c_sh[jc + 4], c_sh[jc + 5]);
            u64 c3 = pack2(c_sh[jc + 6], c_sh[jc + 7]);
            #pragma unroll
            for (int tt = 0; tt < 8; tt++) {
                acc[tt][0] = c0; acc[tt][1] = c1; acc[tt][2] = c2; acc[tt][3] = c3;
            }
        }

        #pragma unroll 1
        for (int i = 0; i < DD; i += 2) {
            const ulonglong2* wr0 = (const ulonglong2*)(Wk + i * H1 + jc);
            const ulonglong2* wr1 = (const ulonglong2*)(Wk + (i + 1) * H1 + jc);
            ulonglong2 wA0 = wr0[0];
            ulonglong2 wB0 = wr0[1];
            ulonglong2 wA1 = wr1[0];
            ulonglong2 wB1 = wr1[1];
            #pragma unroll
            for (int tt = 0; tt < 8; tt++) {
                float2 kv = *(const float2*)(kb + tt * DD + i);
                u64 s0 = pack2(kv.x, kv.x);
                u64 s1 = pack2(kv.y, kv.y);
                fma2(acc[tt][0], s0, wA0.x);
                fma2(acc[tt][1], s0, wA0.y);
                fma2(acc[tt][2], s0, wB0.x);
                fma2(acc[tt][3], s0, wB0.y);
                fma2(acc[tt][0], s1, wA1.x);
                fma2(acc[tt][1], s1, wA1.y);
                fma2(acc[tt][2], s1, wB1.x);
                fma2(acc[tt][3], s1, wB1.y);
            }
        }
        #pragma unroll
        for (int tt = 0; tt < 8; tt++)
            relu_store8(acc[tt], S1 + (tg * 8 + tt) * S1S + jc);
    }
    __syncthreads();

    // ---- GEMM2: S2[200][40] = relu(b2 + S1 @ W2), 4tok x 8g tiles; fold Wf ----
    if (tid < 250) {
        const int tg = tid / 5;
        const int gg = tid - tg * 5;
        const int gc = gg * 8;
        const float* s1b = S1 + (size_t)(tg * 4) * S1S;

        u64 acc[4][4];
        {
            u64 c0 = pack2(b2s[gc],     b2s[gc + 1]);
            u64 c1 = pack2(b2s[gc + 2], b2s[gc + 3]);
            u64 c2 = pack2(b2s[gc + 4], b2s[gc + 5]);
            u64 c3 = pack2(b2s[gc + 6], b2s[gc + 7]);
            #pragma unroll
            for (int tt = 0; tt < 4; tt++) {
                acc[tt][0] = c0; acc[tt][1] = c1; acc[tt][2] = c2; acc[tt][3] = c3;
            }
        }

        #pragma unroll 2
        for (int j = 0; j < H1; j += 4) {
            float sr[4][4];
            *(float4*)sr[0] = *(const float4*)(s1b + 0 * S1S + j);
            *(float4*)sr[1] = *(const float4*)(s1b + 1 * S1S + j);
            *(float4*)sr[2] = *(const float4*)(s1b + 2 * S1S + j);
            *(float4*)sr[3] = *(const float4*)(s1b + 3 * S1S + j);
            #pragma unroll
            for (int ji = 0; ji < 4; ji++) {
                const ulonglong2* wr = (const ulonglong2*)(W2s + (j + ji) * H2 + gc);
                ulonglong2 wA = wr[0];
                ulonglong2 wB = wr[1];
                #pragma unroll
                for (int tt = 0; tt < 4; tt++) {
                    u64 s = pack2(sr[tt][ji], sr[tt][ji]);
                    fma2(acc[tt][0], s, wA.x);
                    fma2(acc[tt][1], s, wA.y);
                    fma2(acc[tt][2], s, wB.x);
                    fma2(acc[tt][3], s, wB.y);
                }
            }
        }
        float wf[8];
        *(float4*)wf       = *(const float4*)(Wfs + gc);
        *(float4*)(wf + 4) = *(const float4*)(Wfs + gc + 4);
        #pragma unroll
        for (int tt = 0; tt < 4; tt++)
            p2[(tg * 4 + tt) * 5 + gg] = relu_dot8(acc[tt], wf);
    }
    __syncthreads();

    // ---- score assembly + softmax ----
    if (tid < TT) {
        float s = bf[0] + ((p2[tid * 5] + p2[tid * 5 + 1]) +
                           (p2[tid * 5 + 2] + p2[tid * 5 + 3]) + p2[tid * 5 + 4]);
        if (mask[(size_t)b * TT + tid] == 0) s = NEG_BIG_F;
        sc[tid] = s;
    }
    __syncthreads();

    float mval = (tid < TT) ? sc[tid] : -3.0e38f;
    #pragma unroll
    for (int o = 16; o; o >>= 1)
        mval = fmaxf(mval, __shfl_xor_sync(0xffffffffu, mval, o));
    if ((tid & 31) == 0) red[tid >> 5] = mval;
    __syncthreads();
    if (tid == 0) {
        float m = red[0];
        #pragma unroll
        for (int w = 1; w < 8; w++) m = fmaxf(m, red[w]);
        mxin[0] = m;
    }
    __syncthreads();
    const float mx = mxin[0];
    float e = (tid < TT) ? __expf(sc[tid] - mx) : 0.0f;
    if (tid < TT) sc[tid] = e;
    float sval = e;
    #pragma unroll
    for (int o = 16; o; o >>= 1)
        sval += __shfl_xor_sync(0xffffffffu, sval, o);
    if ((tid & 31) == 0) red[tid >> 5] = sval;
    __syncthreads();
    if (tid == 0) {
        float smv = 0.0f;
        #pragma unroll
        for (int w = 0; w < 8; w++) smv += red[w];
        mxin[1] = 1.0f / smv;
    }
    __syncthreads();

    // ---- out = attn @ V ----
    const float inv = mxin[1];
    const int dd = tid & 63;
    const int p  = tid >> 6;
    const float* vb = v + (size_t)b * TT * DD;
    float a0 = 0.f, a1 = 0.f;
    const int t0 = p * 50;
    #pragma unroll 5
    for (int t = t0; t < t0 + 50; t += 2) {
        a0 = fmaf(sc[t],     vb[(size_t)t * DD + dd],       a0);
        a1 = fmaf(sc[t + 1], vb[(size_t)(t + 1) * DD + dd], a1);
    }
    part[tid] = a0 + a1;
    __syncthreads();
    if (tid < DD) {
        float r = part[tid] + part[tid + 64] + part[tid + 128] + part[tid + 192];
        out[(size_t)b * DD + tid] = r * inv;
    }
}

extern "C" void kernel_launch(void* const* d_in, const int* in_sizes, int n_in,
                              void* d_out, int out_size)
{
    const float* q    = (const float*)d_in[0];
    const float* k    = (const float*)d_in[1];
    const float* v    = (const float*)d_in[2];
    const int*   mask = (const int*)  d_in[3];
    const float* W1   = (const float*)d_in[4];
    const float* b1   = (const float*)d_in[5];
    const float* W2   = (const float*)d_in[6];
    const float* b2   = (const float*)d_in[7];
    const float* Wf   = (const float*)d_in[8];
    const float* bf   = (const float*)d_in[9];
    float* out = (float*)d_out;

    const int smem_bytes = SMEM_FLOATS * (int)sizeof(float);
    cudaFuncSetAttribute(din_attn_kernel,
                         cudaFuncAttributeMaxDynamicSharedMemorySize, smem_bytes);
    din_attn_kernel<<<BB, 256, smem_bytes>>>(q, k, v, mask, W1, b1, W2, b2, Wf, bf, out);
}